// round 15
// baseline (speedup 1.0000x reference)
#include <cuda_runtime.h>
#include <cuda_fp16.h>
#include <stdint.h>

// ---------------- problem constants (fixed by dataset) ----------------
#define N_NODES 20000
#define E_MAIN  100000
#define E_BND   20000
#define E_TOT   (E_MAIN + E_BND)
#define E_PAD   100096            // E_MAIN rounded up to 128
#define EB_PAD  20096             // E_BND  rounded up to 128
#define ROWS_TOT (E_PAD + EB_PAD) // 120192, multiple of 128
#define WIDTH   32
#define KW      64
#define DEPTH   4

// W row layout (1024 halves): element (i,o) at
//   p(i,o) = i*32 + ((o>>1)&3)*8 + (o>>3)*2 + (o&1)

// ---------------- device scratch (no allocations allowed) ----------------
__device__ float g_h0[N_NODES * WIDTH];
__device__ float g_h [N_NODES * WIDTH];
__device__ float g_agg1[N_NODES * WIDTH];   // unscaled sum, main edges
__device__ float g_agg2[N_NODES * WIDTH];   // unscaled sum, boundary edges
__device__ float g_cnt1[N_NODES];
__device__ float g_cnt2[N_NODES];
__device__ __align__(16) __half g_khid[(size_t)ROWS_TOT * KW];   // 15.4 MB
__device__ __align__(16) __half g_w2t[2][KW * KW];               // w2 transposed [n][k]
__device__ __align__(16) __half g_w3t[2][1024 * KW];             // w3 transposed [n][k]
__device__ __align__(16) __half g_Wh[(size_t)ROWS_TOT * 1024];   // 246 MB per-edge weights
__device__ float g_rootsum[WIDTH * WIDTH];
__device__ float g_biassum[WIDTH];

// ---------------- fused setup: fc1 + zeros + transposes + rootsum -------------
__global__ void setup_kernel(const float* __restrict__ x,
                             const float* __restrict__ fc1w,
                             const float* __restrict__ fc1b,
                             const float* __restrict__ r1, const float* __restrict__ b1,
                             const float* __restrict__ r2, const float* __restrict__ b2,
                             const float* __restrict__ w2a, const float* __restrict__ w2b,
                             const float* __restrict__ w3a, const float* __restrict__ w3b) {
    int i = blockIdx.x * blockDim.x + threadIdx.x;
    if (i < N_NODES * WIDTH) {
        int n = i >> 5, c = i & 31;
        float v = fmaf(x[n], fc1w[c], fc1b[c]);
        g_h0[i] = v;
        g_h[i]  = v;
        g_agg1[i] = 0.f;
        g_agg2[i] = 0.f;
    }
    if (i < KW * 1024) {                     // w3 transpose: [k][n] -> [n][k]
        int k = i >> 10, n = i & 1023;
        g_w3t[0][n * KW + k] = __float2half_rn(w3a[i]);
        g_w3t[1][n * KW + k] = __float2half_rn(w3b[i]);
    }
    if (i < KW * KW) {                       // w2 transpose
        int k = i >> 6, n = i & 63;
        g_w2t[0][n * KW + k] = __float2half_rn(w2a[i]);
        g_w2t[1][n * KW + k] = __float2half_rn(w2b[i]);
    }
    if (i < N_NODES) { g_cnt1[i] = 0.f; g_cnt2[i] = 0.f; }
    if (i < WIDTH * WIDTH) g_rootsum[i] = r1[i] + r2[i];
    if (i < WIDTH)         g_biassum[i] = b1[i] + b2[i];
}

__global__ void count_kernel(const int* __restrict__ ei,
                             const int* __restrict__ eib) {
    int e = blockIdx.x * blockDim.x + threadIdx.x;
    if (e < E_MAIN) {
        atomicAdd(&g_cnt1[ei[E_MAIN + e]], 1.0f);
    } else if (e < E_TOT) {
        int eb = e - E_MAIN;
        atomicAdd(&g_cnt2[eib[E_BND + eb]], 1.0f);
    }
}

// ---------------- kernel MLP via HMMA ----------------
__global__ void __launch_bounds__(256) kermlp_kernel(
    const float* __restrict__ ea1, const float* __restrict__ ea2,
    const float* __restrict__ k1w1, const float* __restrict__ k1b1, const float* __restrict__ k1b2,
    const float* __restrict__ k2w1, const float* __restrict__ k2b1, const float* __restrict__ k2b2)
{
    __shared__ float sea[128 * 6];
    __shared__ float sw1[6 * 64];
    __shared__ float sb1[64];
    __shared__ float sb2[64];
    __shared__ __half As[128 * 72];   // [edge][h1-k], stride 72
    __shared__ __half Bs[64 * 72];    // [n][k ^ swz], stride 72

    int t = threadIdx.x;
    int r0 = blockIdx.x * 128;
    int set = (r0 >= E_PAD) ? 1 : 0;
    int ebase = set ? (r0 - E_PAD) : r0;
    int valid = set ? E_BND : E_MAIN;
    const float* ea = set ? ea2 : ea1;
    const float* w1 = set ? k2w1 : k1w1;
    const float* b1 = set ? k2b1 : k1b1;
    const float* b2 = set ? k2b2 : k1b2;

    for (int i = t; i < 6 * 64; i += 256) sw1[i] = w1[i];
    if (t < 64) { sb1[t] = b1[t]; sb2[t] = b2[t]; }
    #pragma unroll
    for (int i = 0; i < 3; i++) {
        int idx = t + 256 * i;                 // 0..767
        int e = idx / 6, c = idx - e * 6;
        int eg = ebase + e;
        sea[idx] = (eg < valid) ? ea[(size_t)eg * 6 + c] : 0.f;
    }
    #pragma unroll
    for (int i = 0; i < 2; i++) {
        int id = t + 256 * i;                  // 0..511
        int n = id >> 3, c8 = id & 7;
        uint4 v = *(const uint4*)&g_w2t[set][n * KW + c8 * 8];
        int ksw = (c8 * 8) ^ ((n >> 3) * 8);
        *(uint4*)&Bs[n * 72 + ksw] = v;
    }
    __syncthreads();

    // layer1: thread t -> edge t>>1, outputs (t&1)*32..+31
    {
        int e = t >> 1, ob = (t & 1) * 32;
        float a0 = sea[e * 6 + 0], a1 = sea[e * 6 + 1], a2 = sea[e * 6 + 2];
        float a3 = sea[e * 6 + 3], a4 = sea[e * 6 + 4], a5 = sea[e * 6 + 5];
        #pragma unroll
        for (int o = 0; o < 32; o += 2) {
            int oc = ob + o;
            float v0 = sb1[oc], v1 = sb1[oc + 1];
            v0 = fmaf(a0, sw1[0 * 64 + oc], v0); v1 = fmaf(a0, sw1[0 * 64 + oc + 1], v1);
            v0 = fmaf(a1, sw1[1 * 64 + oc], v0); v1 = fmaf(a1, sw1[1 * 64 + oc + 1], v1);
            v0 = fmaf(a2, sw1[2 * 64 + oc], v0); v1 = fmaf(a2, sw1[2 * 64 + oc + 1], v1);
            v0 = fmaf(a3, sw1[3 * 64 + oc], v0); v1 = fmaf(a3, sw1[3 * 64 + oc + 1], v1);
            v0 = fmaf(a4, sw1[4 * 64 + oc], v0); v1 = fmaf(a4, sw1[4 * 64 + oc + 1], v1);
            v0 = fmaf(a5, sw1[5 * 64 + oc], v0); v1 = fmaf(a5, sw1[5 * 64 + oc + 1], v1);
            __half2 p = __floats2half2_rn(fmaxf(v0, 0.f), fmaxf(v1, 0.f));
            *(__half2*)&As[e * 72 + oc] = p;
        }
    }
    __syncthreads();

    int w = t >> 5, lane = t & 31;
    int wr = w * 16;
    int qrow = lane >> 2;
    int qk2  = (lane & 3) * 2;

    float acc[8][4];
    #pragma unroll
    for (int cf = 0; cf < 8; cf++)
        #pragma unroll
        for (int v = 0; v < 4; v++) acc[cf][v] = 0.f;

    #pragma unroll
    for (int ks = 0; ks < 4; ks++) {
        int k0 = ks * 16;
        const __half* ap = &As[(wr + qrow) * 72 + k0 + qk2];
        uint32_t a0 = *(const uint32_t*)ap;
        uint32_t a1 = *(const uint32_t*)(ap + 8 * 72);
        uint32_t a2 = *(const uint32_t*)(ap + 8);
        uint32_t a3 = *(const uint32_t*)(ap + 8 * 72 + 8);
        #pragma unroll
        for (int cf = 0; cf < 8; cf++) {
            int n = cf * 8 + qrow;
            int xorv = cf * 8;
            uint32_t b0 = *(const uint32_t*)&Bs[n * 72 + ((k0 + qk2) ^ xorv)];
            uint32_t b1 = *(const uint32_t*)&Bs[n * 72 + ((k0 + qk2 + 8) ^ xorv)];
            asm volatile(
                "mma.sync.aligned.m16n8k16.row.col.f32.f16.f16.f32 "
                "{%0,%1,%2,%3}, {%4,%5,%6,%7}, {%8,%9}, {%0,%1,%2,%3};"
                : "+f"(acc[cf][0]), "+f"(acc[cf][1]), "+f"(acc[cf][2]), "+f"(acc[cf][3])
                : "r"(a0), "r"(a1), "r"(a2), "r"(a3), "r"(b0), "r"(b1));
        }
    }

    int row0 = r0 + wr + qrow;
    #pragma unroll
    for (int cf = 0; cf < 8; cf++) {
        int col = cf * 8 + (lane & 3) * 2;
        float bb0 = sb2[col], bb1 = sb2[col + 1];
        __half2 p0 = __floats2half2_rn(fmaxf(acc[cf][0] + bb0, 0.f),
                                       fmaxf(acc[cf][1] + bb1, 0.f));
        __half2 p1 = __floats2half2_rn(fmaxf(acc[cf][2] + bb0, 0.f),
                                       fmaxf(acc[cf][3] + bb1, 0.f));
        *(__half2*)&g_khid[(size_t)row0 * 64 + col]       = p0;
        *(__half2*)&g_khid[(size_t)(row0 + 8) * 64 + col] = p1;
    }
}

// ---------------- W = khid @ w3 + b3: 64x128 tile, >=3 CTAs/SM ---------------
__global__ void __launch_bounds__(256, 3) w3gemm_kernel(
    const float* __restrict__ b3a, const float* __restrict__ b3b)
{
    __shared__ __half As[64 * 72];    // [row][k], stride 72
    __shared__ __half Bs[128 * 72];   // [n][k^swz], stride 72
    __shared__ float sbias[128];

    int rb = blockIdx.x, cb = blockIdx.y;
    size_t r0 = (size_t)rb * 64;
    int set = (r0 >= (size_t)E_PAD) ? 1 : 0;
    const float* b3 = set ? b3b : b3a;
    int t = threadIdx.x;

    if (t < 128) sbias[t] = b3[cb * 128 + t];

    // A tile: 64 rows x 64 halves = 512 uint4
    const __half* Ag = g_khid + r0 * 64;
    #pragma unroll
    for (int i = 0; i < 2; i++) {
        int idx = t + 256 * i;                 // 0..511
        int r = idx >> 3, c8 = idx & 7;
        *(uint4*)&As[r * 72 + c8 * 8] = *(const uint4*)&Ag[r * 64 + c8 * 8];
    }
    // B tile: 128 n x 64 k = 1024 uint4
    const __half* Bg = g_w3t[set] + (size_t)cb * 128 * KW;
    #pragma unroll
    for (int i = 0; i < 4; i++) {
        int idx = t + 256 * i;                 // 0..1023
        int n = idx >> 3, c8 = idx & 7;
        uint4 v = *(const uint4*)&Bg[n * KW + c8 * 8];
        int ksw = (c8 * 8) ^ (((n >> 3) & 7) * 8);
        *(uint4*)&Bs[n * 72 + ksw] = v;
    }
    __syncthreads();

    int w = t >> 5, lane = t & 31;
    int wr = (w & 1) * 32;                     // 2 row groups of 32
    int wc = (w >> 1) * 32;                    // 4 col groups of 32
    int qrow = lane >> 2;
    int q4   = lane & 3;

    uint32_t a_smem = (uint32_t)__cvta_generic_to_shared(As);
    uint32_t b_smem = (uint32_t)__cvta_generic_to_shared(Bs);
    int l15 = lane & 15;

    float acc[2][4][4];
    #pragma unroll
    for (int rf = 0; rf < 2; rf++)
        #pragma unroll
        for (int cf = 0; cf < 4; cf++)
            #pragma unroll
            for (int v = 0; v < 4; v++) acc[rf][cf][v] = 0.f;

    #pragma unroll
    for (int ks = 0; ks < 4; ks++) {
        int k0 = ks * 16;
        uint32_t a[2][4], b[4][2];
        #pragma unroll
        for (int rf = 0; rf < 2; rf++) {
            int row = wr + rf * 16 + l15;
            int col = k0 + (lane >> 4) * 8;
            uint32_t addr = a_smem + (uint32_t)(row * 72 + col) * 2;
            asm volatile(
                "ldmatrix.sync.aligned.m8n8.x4.shared.b16 {%0,%1,%2,%3}, [%4];"
                : "=r"(a[rf][0]), "=r"(a[rf][1]), "=r"(a[rf][2]), "=r"(a[rf][3])
                : "r"(addr));
        }
        #pragma unroll
        for (int cf = 0; cf < 4; cf++) {
            int n = wc + cf * 8 + (l15 & 7);
            int kk = k0 + (l15 >> 3) * 8;
            int xorv = ((n >> 3) & 7) * 8;
            uint32_t addr = b_smem + (uint32_t)(n * 72 + (kk ^ xorv)) * 2;
            asm volatile(
                "ldmatrix.sync.aligned.m8n8.x2.shared.b16 {%0,%1}, [%2];"
                : "=r"(b[cf][0]), "=r"(b[cf][1])
                : "r"(addr));
        }
        #pragma unroll
        for (int rf = 0; rf < 2; rf++)
            #pragma unroll
            for (int cf = 0; cf < 4; cf++)
                asm volatile(
                    "mma.sync.aligned.m16n8k16.row.col.f32.f16.f16.f32 "
                    "{%0,%1,%2,%3}, {%4,%5,%6,%7}, {%8,%9}, {%0,%1,%2,%3};"
                    : "+f"(acc[rf][cf][0]), "+f"(acc[rf][cf][1]),
                      "+f"(acc[rf][cf][2]), "+f"(acc[rf][cf][3])
                    : "r"(a[rf][0]), "r"(a[rf][1]), "r"(a[rf][2]), "r"(a[rf][3]),
                      "r"(b[cf][0]), "r"(b[cf][1]));
    }

    int i_idx = cb * 4 + (wc >> 5);
    size_t colbase = (size_t)i_idx * 32 + q4 * 8;
    #pragma unroll
    for (int rf = 0; rf < 2; rf++) {
        int row = wr + rf * 16 + qrow;
        uint4 lo, hi;
        uint32_t* lop = (uint32_t*)&lo;
        uint32_t* hip = (uint32_t*)&hi;
        #pragma unroll
        for (int cf = 0; cf < 4; cf++) {
            int n32 = wc + cf * 8 + q4 * 2;
            float bb0 = sbias[n32], bb1 = sbias[n32 + 1];
            __half2 pl = __floats2half2_rn(acc[rf][cf][0] + bb0, acc[rf][cf][1] + bb1);
            __half2 ph = __floats2half2_rn(acc[rf][cf][2] + bb0, acc[rf][cf][3] + bb1);
            lop[cf] = *(uint32_t*)&pl;
            hip[cf] = *(uint32_t*)&ph;
        }
        *(uint4*)&g_Wh[(r0 + row) * 1024 + colbase]     = lo;
        *(uint4*)&g_Wh[(r0 + row + 8) * 1024 + colbase] = hi;
    }
}

// ---------------- per-edge message (unscaled; scaling in node_update) ---------
__global__ void __launch_bounds__(256) edge_msg_kernel(const int* __restrict__ ei,
                                                       const int* __restrict__ eib)
{
    int e = (blockIdx.x * blockDim.x + threadIdx.x) >> 5;
    int lane = threadIdx.x & 31;
    if (e >= E_TOT) return;

    int src, dst; size_t wrow; float* aggp;
    if (e < E_MAIN) {
        src = ei[e]; dst = ei[E_MAIN + e];
        wrow = (size_t)e;
        aggp = g_agg1;
    } else {
        int eb = e - E_MAIN;
        src = eib[eb]; dst = eib[E_BND + eb];
        wrow = (size_t)E_PAD + eb;
        aggp = g_agg2;
    }

    float hv = g_h[src * WIDTH + lane];
    const __half* __restrict__ Wp = g_Wh + wrow * 1024;
    int q4 = lane & 3, m = lane >> 2;

    float acc[8];
    #pragma unroll
    for (int k = 0; k < 8; k++) acc[k] = 0.f;

    #pragma unroll
    for (int s = 0; s < 4; s++) {
        int i = m + 8 * s;
        uint4 v = *(const uint4*)(Wp + (size_t)i * 32 + q4 * 8);
        float hi = __shfl_sync(0xffffffffu, hv, i);
        float2 f0 = __half22float2(*reinterpret_cast<const __half2*>(&v.x));
        float2 f1 = __half22float2(*reinterpret_cast<const __half2*>(&v.y));
        float2 f2 = __half22float2(*reinterpret_cast<const __half2*>(&v.z));
        float2 f3 = __half22float2(*reinterpret_cast<const __half2*>(&v.w));
        acc[0] = fmaf(f0.x, hi, acc[0]); acc[1] = fmaf(f0.y, hi, acc[1]);
        acc[2] = fmaf(f1.x, hi, acc[2]); acc[3] = fmaf(f1.y, hi, acc[3]);
        acc[4] = fmaf(f2.x, hi, acc[4]); acc[5] = fmaf(f2.y, hi, acc[5]);
        acc[6] = fmaf(f3.x, hi, acc[6]); acc[7] = fmaf(f3.y, hi, acc[7]);
    }
    #pragma unroll
    for (int k = 0; k < 8; k++) {
        acc[k] += __shfl_xor_sync(0xffffffffu, acc[k], 4);
        acc[k] += __shfl_xor_sync(0xffffffffu, acc[k], 8);
        acc[k] += __shfl_xor_sync(0xffffffffu, acc[k], 16);
    }
    float out = acc[0];
    if (m == 1) out = acc[1];
    else if (m == 2) out = acc[2];
    else if (m == 3) out = acc[3];
    else if (m == 4) out = acc[4];
    else if (m == 5) out = acc[5];
    else if (m == 6) out = acc[6];
    else if (m == 7) out = acc[7];
    int o = (m >> 1) * 8 + q4 * 2 + (m & 1);
    atomicAdd(&aggp[dst * WIDTH + o], out);
}

// ---------------- node update: scale both agg sets, root, relu, +h0 -----------
__global__ void __launch_bounds__(256) node_update_kernel(int last,
                                                          const float* __restrict__ fc2w,
                                                          const float* __restrict__ fc2b,
                                                          float* __restrict__ out) {
    int n = (blockIdx.x * blockDim.x + threadIdx.x) >> 5;
    int lane = threadIdx.x & 31;
    if (n >= N_NODES) return;

    float s1 = 1.0f / fmaxf(g_cnt1[n], 1.0f);
    float s2 = 1.0f / fmaxf(g_cnt2[n], 1.0f);
    int idx = n * WIDTH + lane;
    float hv  = g_h[idx];
    float acc = g_agg1[idx] * s1 + g_agg2[idx] * s2 + g_biassum[lane];
    g_agg1[idx] = 0.f;
    g_agg2[idx] = 0.f;
    #pragma unroll
    for (int i = 0; i < 32; i++) {
        float hi = __shfl_sync(0xffffffffu, hv, i);
        acc = fmaf(hi, g_rootsum[i * 32 + lane], acc);
    }
    float hnew = fmaxf(acc, 0.f) + g_h0[idx];
    g_h[idx] = hnew;

    if (last) {
        float v = hnew * fc2w[lane];
        #pragma unroll
        for (int off = 16; off > 0; off >>= 1)
            v += __shfl_xor_sync(0xffffffffu, v, off);
        if (lane == 0) out[n] = v + fc2b[0];
    }
}

// ---------------- host orchestration ----------------
extern "C" void kernel_launch(void* const* d_in, const int* in_sizes, int n_in,
                              void* d_out, int out_size) {
    const float* x    = (const float*)d_in[0];
    const int*   ei   = (const int*)  d_in[1];
    const float* ea   = (const float*)d_in[2];
    const int*   eib  = (const int*)  d_in[3];
    const float* eab  = (const float*)d_in[4];
    const float* fc1w = (const float*)d_in[5];
    const float* fc1b = (const float*)d_in[6];
    const float* fc2w = (const float*)d_in[7];
    const float* fc2b = (const float*)d_in[8];
    const float* k1w1 = (const float*)d_in[9];
    const float* k1b1 = (const float*)d_in[10];
    const float* k1w2 = (const float*)d_in[11];
    const float* k1b2 = (const float*)d_in[12];
    const float* k1w3 = (const float*)d_in[13];
    const float* k1b3 = (const float*)d_in[14];
    const float* root1= (const float*)d_in[15];
    const float* bias1= (const float*)d_in[16];
    const float* k2w1 = (const float*)d_in[17];
    const float* k2b1 = (const float*)d_in[18];
    const float* k2w2 = (const float*)d_in[19];
    const float* k2b2 = (const float*)d_in[20];
    const float* k2w3 = (const float*)d_in[21];
    const float* k2b3 = (const float*)d_in[22];
    const float* root2= (const float*)d_in[23];
    const float* bias2= (const float*)d_in[24];
    float* out = (float*)d_out;

    // ncu profiles launch #4 -> w3gemm_kernel (verify occupancy fix)
    setup_kernel<<<(N_NODES * WIDTH + 255) / 256, 256>>>(
        x, fc1w, fc1b, root1, bias1, root2, bias2,
        k1w2, k2w2, k1w3, k2w3);                                               // 1
    kermlp_kernel<<<ROWS_TOT / 128, 256>>>(ea, eab,
                                           k1w1, k1b1, k1b2,
                                           k2w1, k2b1, k2b2);                  // 2
    count_kernel<<<(E_TOT + 255) / 256, 256>>>(ei, eib);                       // 3
    dim3 ggrid(ROWS_TOT / 64, 1024 / 128);
    w3gemm_kernel<<<ggrid, 256>>>(k1b3, k2b3);                                 // 4

    for (int d = 0; d < DEPTH; d++) {
        edge_msg_kernel<<<(E_TOT * 32 + 255) / 256, 256>>>(ei, eib);
        node_update_kernel<<<(N_NODES * 32 + 255) / 256, 256>>>(
            d == DEPTH - 1 ? 1 : 0, fc2w, fc2b, out);
    }
}

// round 16
// speedup vs baseline: 1.0188x; 1.0188x over previous
#include <cuda_runtime.h>
#include <cuda_fp16.h>
#include <stdint.h>

// ---------------- problem constants (fixed by dataset) ----------------
#define N_NODES 20000
#define E_MAIN  100000
#define E_BND   20000
#define E_TOT   (E_MAIN + E_BND)
#define E_PAD   100096            // E_MAIN rounded up to 128
#define EB_PAD  20096             // E_BND  rounded up to 128
#define ROWS_TOT (E_PAD + EB_PAD) // 120192, multiple of 128
#define WIDTH   32
#define KW      64
#define DEPTH   4

// W row layout (1024 halves): element (i,o) at
//   p(i,o) = i*32 + ((o>>1)&3)*8 + (o>>3)*2 + (o&1)

// ---------------- device scratch (no allocations allowed) ----------------
__device__ float g_h0[N_NODES * WIDTH];
__device__ float g_h [N_NODES * WIDTH];
__device__ float g_agg1[N_NODES * WIDTH];   // unscaled sum, main edges
__device__ float g_agg2[N_NODES * WIDTH];   // unscaled sum, boundary edges
__device__ float g_cnt1[N_NODES];
__device__ float g_cnt2[N_NODES];
__device__ __align__(16) __half g_khid[(size_t)ROWS_TOT * KW];   // 15.4 MB
__device__ __align__(16) __half g_w2t[2][KW * KW];               // w2 transposed [n][k]
__device__ __align__(16) __half g_w3t[2][1024 * KW];             // w3 transposed [n][k]
__device__ __align__(16) __half g_Wh[(size_t)ROWS_TOT * 1024];   // 246 MB per-edge weights
__device__ float g_rootsum[WIDTH * WIDTH];
__device__ float g_biassum[WIDTH];

// ---------------- fused setup: fc1 + zeros + transposes + rootsum -------------
__global__ void setup_kernel(const float* __restrict__ x,
                             const float* __restrict__ fc1w,
                             const float* __restrict__ fc1b,
                             const float* __restrict__ r1, const float* __restrict__ b1,
                             const float* __restrict__ r2, const float* __restrict__ b2,
                             const float* __restrict__ w2a, const float* __restrict__ w2b,
                             const float* __restrict__ w3a, const float* __restrict__ w3b) {
    int i = blockIdx.x * blockDim.x + threadIdx.x;
    if (i < N_NODES * WIDTH) {
        int n = i >> 5, c = i & 31;
        float v = fmaf(x[n], fc1w[c], fc1b[c]);
        g_h0[i] = v;
        g_h[i]  = v;
        g_agg1[i] = 0.f;
        g_agg2[i] = 0.f;
    }
    if (i < KW * 1024) {                     // w3 transpose: [k][n] -> [n][k]
        int k = i >> 10, n = i & 1023;
        g_w3t[0][n * KW + k] = __float2half_rn(w3a[i]);
        g_w3t[1][n * KW + k] = __float2half_rn(w3b[i]);
    }
    if (i < KW * KW) {                       // w2 transpose
        int k = i >> 6, n = i & 63;
        g_w2t[0][n * KW + k] = __float2half_rn(w2a[i]);
        g_w2t[1][n * KW + k] = __float2half_rn(w2b[i]);
    }
    if (i < N_NODES) { g_cnt1[i] = 0.f; g_cnt2[i] = 0.f; }
    if (i < WIDTH * WIDTH) g_rootsum[i] = r1[i] + r2[i];
    if (i < WIDTH)         g_biassum[i] = b1[i] + b2[i];
}

__global__ void count_kernel(const int* __restrict__ ei,
                             const int* __restrict__ eib) {
    int e = blockIdx.x * blockDim.x + threadIdx.x;
    if (e < E_MAIN) {
        atomicAdd(&g_cnt1[ei[E_MAIN + e]], 1.0f);
    } else if (e < E_TOT) {
        int eb = e - E_MAIN;
        atomicAdd(&g_cnt2[eib[E_BND + eb]], 1.0f);
    }
}

// ---------------- kernel MLP via HMMA ----------------
__global__ void __launch_bounds__(256) kermlp_kernel(
    const float* __restrict__ ea1, const float* __restrict__ ea2,
    const float* __restrict__ k1w1, const float* __restrict__ k1b1, const float* __restrict__ k1b2,
    const float* __restrict__ k2w1, const float* __restrict__ k2b1, const float* __restrict__ k2b2)
{
    __shared__ float sea[128 * 6];
    __shared__ float sw1[6 * 64];
    __shared__ float sb1[64];
    __shared__ float sb2[64];
    __shared__ __half As[128 * 72];   // [edge][h1-k], stride 72
    __shared__ __half Bs[64 * 72];    // [n][k ^ swz], stride 72

    int t = threadIdx.x;
    int r0 = blockIdx.x * 128;
    int set = (r0 >= E_PAD) ? 1 : 0;
    int ebase = set ? (r0 - E_PAD) : r0;
    int valid = set ? E_BND : E_MAIN;
    const float* ea = set ? ea2 : ea1;
    const float* w1 = set ? k2w1 : k1w1;
    const float* b1 = set ? k2b1 : k1b1;
    const float* b2 = set ? k2b2 : k1b2;

    for (int i = t; i < 6 * 64; i += 256) sw1[i] = w1[i];
    if (t < 64) { sb1[t] = b1[t]; sb2[t] = b2[t]; }
    #pragma unroll
    for (int i = 0; i < 3; i++) {
        int idx = t + 256 * i;                 // 0..767
        int e = idx / 6, c = idx - e * 6;
        int eg = ebase + e;
        sea[idx] = (eg < valid) ? ea[(size_t)eg * 6 + c] : 0.f;
    }
    #pragma unroll
    for (int i = 0; i < 2; i++) {
        int id = t + 256 * i;                  // 0..511
        int n = id >> 3, c8 = id & 7;
        uint4 v = *(const uint4*)&g_w2t[set][n * KW + c8 * 8];
        int ksw = (c8 * 8) ^ ((n >> 3) * 8);
        *(uint4*)&Bs[n * 72 + ksw] = v;
    }
    __syncthreads();

    // layer1: thread t -> edge t>>1, outputs (t&1)*32..+31
    {
        int e = t >> 1, ob = (t & 1) * 32;
        float a0 = sea[e * 6 + 0], a1 = sea[e * 6 + 1], a2 = sea[e * 6 + 2];
        float a3 = sea[e * 6 + 3], a4 = sea[e * 6 + 4], a5 = sea[e * 6 + 5];
        #pragma unroll
        for (int o = 0; o < 32; o += 2) {
            int oc = ob + o;
            float v0 = sb1[oc], v1 = sb1[oc + 1];
            v0 = fmaf(a0, sw1[0 * 64 + oc], v0); v1 = fmaf(a0, sw1[0 * 64 + oc + 1], v1);
            v0 = fmaf(a1, sw1[1 * 64 + oc], v0); v1 = fmaf(a1, sw1[1 * 64 + oc + 1], v1);
            v0 = fmaf(a2, sw1[2 * 64 + oc], v0); v1 = fmaf(a2, sw1[2 * 64 + oc + 1], v1);
            v0 = fmaf(a3, sw1[3 * 64 + oc], v0); v1 = fmaf(a3, sw1[3 * 64 + oc + 1], v1);
            v0 = fmaf(a4, sw1[4 * 64 + oc], v0); v1 = fmaf(a4, sw1[4 * 64 + oc + 1], v1);
            v0 = fmaf(a5, sw1[5 * 64 + oc], v0); v1 = fmaf(a5, sw1[5 * 64 + oc + 1], v1);
            __half2 p = __floats2half2_rn(fmaxf(v0, 0.f), fmaxf(v1, 0.f));
            *(__half2*)&As[e * 72 + oc] = p;
        }
    }
    __syncthreads();

    int w = t >> 5, lane = t & 31;
    int wr = w * 16;
    int qrow = lane >> 2;
    int qk2  = (lane & 3) * 2;

    float acc[8][4];
    #pragma unroll
    for (int cf = 0; cf < 8; cf++)
        #pragma unroll
        for (int v = 0; v < 4; v++) acc[cf][v] = 0.f;

    #pragma unroll
    for (int ks = 0; ks < 4; ks++) {
        int k0 = ks * 16;
        const __half* ap = &As[(wr + qrow) * 72 + k0 + qk2];
        uint32_t a0 = *(const uint32_t*)ap;
        uint32_t a1 = *(const uint32_t*)(ap + 8 * 72);
        uint32_t a2 = *(const uint32_t*)(ap + 8);
        uint32_t a3 = *(const uint32_t*)(ap + 8 * 72 + 8);
        #pragma unroll
        for (int cf = 0; cf < 8; cf++) {
            int n = cf * 8 + qrow;
            int xorv = cf * 8;
            uint32_t b0 = *(const uint32_t*)&Bs[n * 72 + ((k0 + qk2) ^ xorv)];
            uint32_t b1 = *(const uint32_t*)&Bs[n * 72 + ((k0 + qk2 + 8) ^ xorv)];
            asm volatile(
                "mma.sync.aligned.m16n8k16.row.col.f32.f16.f16.f32 "
                "{%0,%1,%2,%3}, {%4,%5,%6,%7}, {%8,%9}, {%0,%1,%2,%3};"
                : "+f"(acc[cf][0]), "+f"(acc[cf][1]), "+f"(acc[cf][2]), "+f"(acc[cf][3])
                : "r"(a0), "r"(a1), "r"(a2), "r"(a3), "r"(b0), "r"(b1));
        }
    }

    int row0 = r0 + wr + qrow;
    #pragma unroll
    for (int cf = 0; cf < 8; cf++) {
        int col = cf * 8 + (lane & 3) * 2;
        float bb0 = sb2[col], bb1 = sb2[col + 1];
        __half2 p0 = __floats2half2_rn(fmaxf(acc[cf][0] + bb0, 0.f),
                                       fmaxf(acc[cf][1] + bb1, 0.f));
        __half2 p1 = __floats2half2_rn(fmaxf(acc[cf][2] + bb0, 0.f),
                                       fmaxf(acc[cf][3] + bb1, 0.f));
        *(__half2*)&g_khid[(size_t)row0 * 64 + col]       = p0;
        *(__half2*)&g_khid[(size_t)(row0 + 8) * 64 + col] = p1;
    }
}

// ---------------- W = khid @ w3 + b3: 128x128 tile, ldmatrix, cb-fast grid ----
// blockIdx.x = cb (8 col blocks), blockIdx.y = rb -> consecutive CTAs share
// the same khid A tile (L2 hit); w3t (128 KB) stays L2-resident.
__global__ void __launch_bounds__(256) w3gemm_kernel(
    const float* __restrict__ b3a, const float* __restrict__ b3b)
{
    __shared__ __half As[128 * 72];   // [row][k], stride 72
    __shared__ __half Bs[128 * 72];   // [n][k^swz], stride 72
    __shared__ float sbias[128];

    int cb = blockIdx.x, rb = blockIdx.y;
    size_t r0 = (size_t)rb * 128;
    int set = (r0 >= (size_t)E_PAD) ? 1 : 0;
    const float* b3 = set ? b3b : b3a;
    int t = threadIdx.x;

    if (t < 128) sbias[t] = b3[cb * 128 + t];

    const __half* Ag = g_khid + r0 * 64;
    #pragma unroll
    for (int i = 0; i < 4; i++) {
        int idx = t + 256 * i;
        int r = idx >> 3, c8 = idx & 7;
        *(uint4*)&As[r * 72 + c8 * 8] = *(const uint4*)&Ag[r * 64 + c8 * 8];
    }
    const __half* Bg = g_w3t[set] + (size_t)cb * 128 * KW;
    #pragma unroll
    for (int i = 0; i < 4; i++) {
        int idx = t + 256 * i;                 // 0..1023
        int n = idx >> 3, c8 = idx & 7;
        uint4 v = *(const uint4*)&Bg[n * KW + c8 * 8];
        int ksw = (c8 * 8) ^ (((n >> 3) & 7) * 8);
        *(uint4*)&Bs[n * 72 + ksw] = v;
    }
    __syncthreads();

    int w = t >> 5, lane = t & 31;
    int wr = (w & 1) * 64;
    int wc = (w >> 1) * 32;
    int qrow = lane >> 2;
    int q4   = lane & 3;

    uint32_t a_smem = (uint32_t)__cvta_generic_to_shared(As);
    uint32_t b_smem = (uint32_t)__cvta_generic_to_shared(Bs);
    int l15 = lane & 15;

    float acc[4][4][4];
    #pragma unroll
    for (int rf = 0; rf < 4; rf++)
        #pragma unroll
        for (int cf = 0; cf < 4; cf++)
            #pragma unroll
            for (int v = 0; v < 4; v++) acc[rf][cf][v] = 0.f;

    #pragma unroll
    for (int ks = 0; ks < 4; ks++) {
        int k0 = ks * 16;
        uint32_t a[4][4], b[4][2];
        #pragma unroll
        for (int rf = 0; rf < 4; rf++) {
            int row = wr + rf * 16 + l15;
            int col = k0 + (lane >> 4) * 8;
            uint32_t addr = a_smem + (uint32_t)(row * 72 + col) * 2;
            asm volatile(
                "ldmatrix.sync.aligned.m8n8.x4.shared.b16 {%0,%1,%2,%3}, [%4];"
                : "=r"(a[rf][0]), "=r"(a[rf][1]), "=r"(a[rf][2]), "=r"(a[rf][3])
                : "r"(addr));
        }
        #pragma unroll
        for (int cf = 0; cf < 4; cf++) {
            int n = wc + cf * 8 + (l15 & 7);
            int kk = k0 + (l15 >> 3) * 8;
            int xorv = ((n >> 3) & 7) * 8;
            uint32_t addr = b_smem + (uint32_t)(n * 72 + (kk ^ xorv)) * 2;
            asm volatile(
                "ldmatrix.sync.aligned.m8n8.x2.shared.b16 {%0,%1}, [%2];"
                : "=r"(b[cf][0]), "=r"(b[cf][1])
                : "r"(addr));
        }
        #pragma unroll
        for (int rf = 0; rf < 4; rf++)
            #pragma unroll
            for (int cf = 0; cf < 4; cf++)
                asm volatile(
                    "mma.sync.aligned.m16n8k16.row.col.f32.f16.f16.f32 "
                    "{%0,%1,%2,%3}, {%4,%5,%6,%7}, {%8,%9}, {%0,%1,%2,%3};"
                    : "+f"(acc[rf][cf][0]), "+f"(acc[rf][cf][1]),
                      "+f"(acc[rf][cf][2]), "+f"(acc[rf][cf][3])
                    : "r"(a[rf][0]), "r"(a[rf][1]), "r"(a[rf][2]), "r"(a[rf][3]),
                      "r"(b[cf][0]), "r"(b[cf][1]));
    }

    int i_idx = cb * 4 + (wc >> 5);
    size_t colbase = (size_t)i_idx * 32 + q4 * 8;
    #pragma unroll
    for (int rf = 0; rf < 4; rf++) {
        int row = wr + rf * 16 + qrow;
        uint4 lo, hi;
        uint32_t* lop = (uint32_t*)&lo;
        uint32_t* hip = (uint32_t*)&hi;
        #pragma unroll
        for (int cf = 0; cf < 4; cf++) {
            int n32 = wc + cf * 8 + q4 * 2;
            float bb0 = sbias[n32], bb1 = sbias[n32 + 1];
            __half2 pl = __floats2half2_rn(acc[rf][cf][0] + bb0, acc[rf][cf][1] + bb1);
            __half2 ph = __floats2half2_rn(acc[rf][cf][2] + bb0, acc[rf][cf][3] + bb1);
            lop[cf] = *(uint32_t*)&pl;
            hip[cf] = *(uint32_t*)&ph;
        }
        *(uint4*)&g_Wh[(r0 + row) * 1024 + colbase]     = lo;
        *(uint4*)&g_Wh[(r0 + row + 8) * 1024 + colbase] = hi;
    }
}

// ---------------- per-edge message (unscaled; scaling in node_update) ---------
__global__ void __launch_bounds__(256) edge_msg_kernel(const int* __restrict__ ei,
                                                       const int* __restrict__ eib)
{
    int e = (blockIdx.x * blockDim.x + threadIdx.x) >> 5;
    int lane = threadIdx.x & 31;
    if (e >= E_TOT) return;

    int src, dst; size_t wrow; float* aggp;
    if (e < E_MAIN) {
        src = ei[e]; dst = ei[E_MAIN + e];
        wrow = (size_t)e;
        aggp = g_agg1;
    } else {
        int eb = e - E_MAIN;
        src = eib[eb]; dst = eib[E_BND + eb];
        wrow = (size_t)E_PAD + eb;
        aggp = g_agg2;
    }

    float hv = g_h[src * WIDTH + lane];
    const __half* __restrict__ Wp = g_Wh + wrow * 1024;
    int q4 = lane & 3, m = lane >> 2;

    float acc[8];
    #pragma unroll
    for (int k = 0; k < 8; k++) acc[k] = 0.f;

    #pragma unroll
    for (int s = 0; s < 4; s++) {
        int i = m + 8 * s;
        uint4 v = *(const uint4*)(Wp + (size_t)i * 32 + q4 * 8);
        float hi = __shfl_sync(0xffffffffu, hv, i);
        float2 f0 = __half22float2(*reinterpret_cast<const __half2*>(&v.x));
        float2 f1 = __half22float2(*reinterpret_cast<const __half2*>(&v.y));
        float2 f2 = __half22float2(*reinterpret_cast<const __half2*>(&v.z));
        float2 f3 = __half22float2(*reinterpret_cast<const __half2*>(&v.w));
        acc[0] = fmaf(f0.x, hi, acc[0]); acc[1] = fmaf(f0.y, hi, acc[1]);
        acc[2] = fmaf(f1.x, hi, acc[2]); acc[3] = fmaf(f1.y, hi, acc[3]);
        acc[4] = fmaf(f2.x, hi, acc[4]); acc[5] = fmaf(f2.y, hi, acc[5]);
        acc[6] = fmaf(f3.x, hi, acc[6]); acc[7] = fmaf(f3.y, hi, acc[7]);
    }
    #pragma unroll
    for (int k = 0; k < 8; k++) {
        acc[k] += __shfl_xor_sync(0xffffffffu, acc[k], 4);
        acc[k] += __shfl_xor_sync(0xffffffffu, acc[k], 8);
        acc[k] += __shfl_xor_sync(0xffffffffu, acc[k], 16);
    }
    float out = acc[0];
    if (m == 1) out = acc[1];
    else if (m == 2) out = acc[2];
    else if (m == 3) out = acc[3];
    else if (m == 4) out = acc[4];
    else if (m == 5) out = acc[5];
    else if (m == 6) out = acc[6];
    else if (m == 7) out = acc[7];
    int o = (m >> 1) * 8 + q4 * 2 + (m & 1);
    atomicAdd(&aggp[dst * WIDTH + o], out);
}

// ---------------- node update: scale both agg sets, root, relu, +h0 -----------
__global__ void __launch_bounds__(256) node_update_kernel(int last,
                                                          const float* __restrict__ fc2w,
                                                          const float* __restrict__ fc2b,
                                                          float* __restrict__ out) {
    int n = (blockIdx.x * blockDim.x + threadIdx.x) >> 5;
    int lane = threadIdx.x & 31;
    if (n >= N_NODES) return;

    float s1 = 1.0f / fmaxf(g_cnt1[n], 1.0f);
    float s2 = 1.0f / fmaxf(g_cnt2[n], 1.0f);
    int idx = n * WIDTH + lane;
    float hv  = g_h[idx];
    float acc = g_agg1[idx] * s1 + g_agg2[idx] * s2 + g_biassum[lane];
    g_agg1[idx] = 0.f;
    g_agg2[idx] = 0.f;
    #pragma unroll
    for (int i = 0; i < 32; i++) {
        float hi = __shfl_sync(0xffffffffu, hv, i);
        acc = fmaf(hi, g_rootsum[i * 32 + lane], acc);
    }
    float hnew = fmaxf(acc, 0.f) + g_h0[idx];
    g_h[idx] = hnew;

    if (last) {
        float v = hnew * fc2w[lane];
        #pragma unroll
        for (int off = 16; off > 0; off >>= 1)
            v += __shfl_xor_sync(0xffffffffu, v, off);
        if (lane == 0) out[n] = v + fc2b[0];
    }
}

// ---------------- host orchestration ----------------
extern "C" void kernel_launch(void* const* d_in, const int* in_sizes, int n_in,
                              void* d_out, int out_size) {
    const float* x    = (const float*)d_in[0];
    const int*   ei   = (const int*)  d_in[1];
    const float* ea   = (const float*)d_in[2];
    const int*   eib  = (const int*)  d_in[3];
    const float* eab  = (const float*)d_in[4];
    const float* fc1w = (const float*)d_in[5];
    const float* fc1b = (const float*)d_in[6];
    const float* fc2w = (const float*)d_in[7];
    const float* fc2b = (const float*)d_in[8];
    const float* k1w1 = (const float*)d_in[9];
    const float* k1b1 = (const float*)d_in[10];
    const float* k1w2 = (const float*)d_in[11];
    const float* k1b2 = (const float*)d_in[12];
    const float* k1w3 = (const float*)d_in[13];
    const float* k1b3 = (const float*)d_in[14];
    const float* root1= (const float*)d_in[15];
    const float* bias1= (const float*)d_in[16];
    const float* k2w1 = (const float*)d_in[17];
    const float* k2b1 = (const float*)d_in[18];
    const float* k2w2 = (const float*)d_in[19];
    const float* k2b2 = (const float*)d_in[20];
    const float* k2w3 = (const float*)d_in[21];
    const float* k2b3 = (const float*)d_in[22];
    const float* root2= (const float*)d_in[23];
    const float* bias2= (const float*)d_in[24];
    float* out = (float*)d_out;

    // ncu profiles launch #4 -> w3gemm_kernel (verify grid-order fix)
    setup_kernel<<<(N_NODES * WIDTH + 255) / 256, 256>>>(
        x, fc1w, fc1b, root1, bias1, root2, bias2,
        k1w2, k2w2, k1w3, k2w3);                                               // 1
    kermlp_kernel<<<ROWS_TOT / 128, 256>>>(ea, eab,
                                           k1w1, k1b1, k1b2,
                                           k2w1, k2b1, k2b2);                  // 2
    count_kernel<<<(E_TOT + 255) / 256, 256>>>(ei, eib);                       // 3
    dim3 ggrid(1024 / 128, ROWS_TOT / 128);   // x = cb (fast), y = rb
    w3gemm_kernel<<<ggrid, 256>>>(k1b3, k2b3);                                 // 4

    for (int d = 0; d < DEPTH; d++) {
        edge_msg_kernel<<<(E_TOT * 32 + 255) / 256, 256>>>(ei, eib);
        node_update_kernel<<<(N_NODES * 32 + 255) / 256, 256>>>(
            d == DEPTH - 1 ? 1 : 0, fc2w, fc2b, out);
    }
}

// round 17
// speedup vs baseline: 1.0487x; 1.0294x over previous
#include <cuda_runtime.h>
#include <cuda_fp16.h>
#include <stdint.h>

// ---------------- problem constants (fixed by dataset) ----------------
#define N_NODES 20000
#define E_MAIN  100000
#define E_BND   20000
#define E_TOT   (E_MAIN + E_BND)
#define E_PAD   100096            // E_MAIN rounded up to 128
#define EB_PAD  20096             // E_BND  rounded up to 128
#define ROWS_TOT (E_PAD + EB_PAD) // 120192, multiple of 128
#define WIDTH   32
#define KW      64
#define DEPTH   4

// W row layout (1024 halves): element (i,o) at
//   p(i,o) = i*32 + ((o>>1)&3)*8 + (o>>3)*2 + (o&1)

// ---------------- device scratch (no allocations allowed) ----------------
__device__ float g_h0[N_NODES * WIDTH];
__device__ float g_h [N_NODES * WIDTH];
__device__ float g_agg1[N_NODES * WIDTH];   // unscaled sum, main edges
__device__ float g_agg2[N_NODES * WIDTH];   // unscaled sum, boundary edges
__device__ float g_cnt1[N_NODES];
__device__ float g_cnt2[N_NODES];
__device__ __align__(16) __half g_w2t[2][KW * KW];               // w2 transposed [n][k]
__device__ __align__(16) __half g_w3t[2][1024 * KW];             // w3 transposed [n][k]
__device__ __align__(16) __half g_Wh[(size_t)ROWS_TOT * 1024];   // 246 MB per-edge weights
__device__ float g_rootsum[WIDTH * WIDTH];
__device__ float g_biassum[WIDTH];

// ---------------- setup A: fc1 + zero agg + zero cnt ----------------
__global__ void setupA_kernel(const float* __restrict__ x,
                              const float* __restrict__ fc1w,
                              const float* __restrict__ fc1b) {
    int i = blockIdx.x * blockDim.x + threadIdx.x;
    if (i < N_NODES * WIDTH) {
        int n = i >> 5, c = i & 31;
        float v = fmaf(x[n], fc1w[c], fc1b[c]);
        g_h0[i] = v;
        g_h[i]  = v;
        g_agg1[i] = 0.f;
        g_agg2[i] = 0.f;
    }
    if (i < N_NODES) { g_cnt1[i] = 0.f; g_cnt2[i] = 0.f; }
}

// ---------------- setup B: transposes + rootsum ----------------
__global__ void setupB_kernel(const float* __restrict__ r1, const float* __restrict__ b1,
                              const float* __restrict__ r2, const float* __restrict__ b2,
                              const float* __restrict__ w2a, const float* __restrict__ w2b,
                              const float* __restrict__ w3a, const float* __restrict__ w3b) {
    int i = blockIdx.x * blockDim.x + threadIdx.x;
    if (i < KW * 1024) {                     // w3 transpose: [k][n] -> [n][k]
        int k = i >> 10, n = i & 1023;
        g_w3t[0][n * KW + k] = __float2half_rn(w3a[i]);
        g_w3t[1][n * KW + k] = __float2half_rn(w3b[i]);
    }
    if (i < KW * KW) {                       // w2 transpose
        int k = i >> 6, n = i & 63;
        g_w2t[0][n * KW + k] = __float2half_rn(w2a[i]);
        g_w2t[1][n * KW + k] = __float2half_rn(w2b[i]);
    }
    if (i < WIDTH * WIDTH) g_rootsum[i] = r1[i] + r2[i];
    if (i < WIDTH)         g_biassum[i] = b1[i] + b2[i];
}

__global__ void count_kernel(const int* __restrict__ ei,
                             const int* __restrict__ eib) {
    int e = blockIdx.x * blockDim.x + threadIdx.x;
    if (e < E_MAIN) {
        atomicAdd(&g_cnt1[ei[E_MAIN + e]], 1.0f);
    } else if (e < E_TOT) {
        int eb = e - E_MAIN;
        atomicAdd(&g_cnt2[eib[E_BND + eb]], 1.0f);
    }
}

// ---------------- FUSED: kernel-MLP + W-GEMM per 128-edge block ---------------
// Phase 1: edge_attr -> khid (layer1 FMA + layer2 HMMA), result kept in smem As.
// Phase 2: loop over 8 column blocks of W: Bs <- w3t tile, HMMA, direct store.
__global__ void __launch_bounds__(256) fused_kernel(
    const float* __restrict__ ea1, const float* __restrict__ ea2,
    const float* __restrict__ k1w1, const float* __restrict__ k1b1, const float* __restrict__ k1b2,
    const float* __restrict__ k2w1, const float* __restrict__ k2b1, const float* __restrict__ k2b2,
    const float* __restrict__ b3a, const float* __restrict__ b3b)
{
    __shared__ float sea[128 * 6];
    __shared__ float sw1[6 * 64];
    __shared__ float sb1[64];
    __shared__ float sb2[64];
    __shared__ __half As[128 * 72];   // layer1 out, then khid, stride 72
    __shared__ __half Bs[128 * 72];   // w2t tile (rows 0..63), then w3t tiles
    __shared__ float sbias[128];

    int t = threadIdx.x;
    int r0 = blockIdx.x * 128;
    int set = (r0 >= E_PAD) ? 1 : 0;
    int ebase = set ? (r0 - E_PAD) : r0;
    int valid = set ? E_BND : E_MAIN;
    const float* ea = set ? ea2 : ea1;
    const float* w1 = set ? k2w1 : k1w1;
    const float* b1 = set ? k2b1 : k1b1;
    const float* b2 = set ? k2b2 : k1b2;
    const float* b3 = set ? b3b : b3a;

    // ---- phase 1 loads ----
    for (int i = t; i < 6 * 64; i += 256) sw1[i] = w1[i];
    if (t < 64) { sb1[t] = b1[t]; sb2[t] = b2[t]; }
    #pragma unroll
    for (int i = 0; i < 3; i++) {
        int idx = t + 256 * i;                 // 0..767
        int e = idx / 6, c = idx - e * 6;
        int eg = ebase + e;
        sea[idx] = (eg < valid) ? ea[(size_t)eg * 6 + c] : 0.f;
    }
    #pragma unroll
    for (int i = 0; i < 2; i++) {
        int id = t + 256 * i;                  // 0..511
        int n = id >> 3, c8 = id & 7;
        uint4 v = *(const uint4*)&g_w2t[set][n * KW + c8 * 8];
        int ksw = (c8 * 8) ^ ((n >> 3) * 8);
        *(uint4*)&Bs[n * 72 + ksw] = v;
    }
    __syncthreads();

    // ---- layer1: thread t -> edge t>>1, outputs (t&1)*32..+31 ----
    {
        int e = t >> 1, ob = (t & 1) * 32;
        float a0 = sea[e * 6 + 0], a1 = sea[e * 6 + 1], a2 = sea[e * 6 + 2];
        float a3 = sea[e * 6 + 3], a4 = sea[e * 6 + 4], a5 = sea[e * 6 + 5];
        #pragma unroll
        for (int o = 0; o < 32; o += 2) {
            int oc = ob + o;
            float v0 = sb1[oc], v1 = sb1[oc + 1];
            v0 = fmaf(a0, sw1[0 * 64 + oc], v0); v1 = fmaf(a0, sw1[0 * 64 + oc + 1], v1);
            v0 = fmaf(a1, sw1[1 * 64 + oc], v0); v1 = fmaf(a1, sw1[1 * 64 + oc + 1], v1);
            v0 = fmaf(a2, sw1[2 * 64 + oc], v0); v1 = fmaf(a2, sw1[2 * 64 + oc + 1], v1);
            v0 = fmaf(a3, sw1[3 * 64 + oc], v0); v1 = fmaf(a3, sw1[3 * 64 + oc + 1], v1);
            v0 = fmaf(a4, sw1[4 * 64 + oc], v0); v1 = fmaf(a4, sw1[4 * 64 + oc + 1], v1);
            v0 = fmaf(a5, sw1[5 * 64 + oc], v0); v1 = fmaf(a5, sw1[5 * 64 + oc + 1], v1);
            __half2 p = __floats2half2_rn(fmaxf(v0, 0.f), fmaxf(v1, 0.f));
            *(__half2*)&As[e * 72 + oc] = p;
        }
    }
    __syncthreads();

    int w = t >> 5, lane = t & 31;
    int qrow = lane >> 2;
    int q4   = lane & 3;
    int qk2  = q4 * 2;

    // ---- layer2: warp w owns As rows w*16..+15 (reads+writes warp-private) ----
    {
        int wr = w * 16;
        float acc[8][4];
        #pragma unroll
        for (int cf = 0; cf < 8; cf++)
            #pragma unroll
            for (int v = 0; v < 4; v++) acc[cf][v] = 0.f;

        #pragma unroll
        for (int ks = 0; ks < 4; ks++) {
            int k0 = ks * 16;
            const __half* ap = &As[(wr + qrow) * 72 + k0 + qk2];
            uint32_t a0 = *(const uint32_t*)ap;
            uint32_t a1 = *(const uint32_t*)(ap + 8 * 72);
            uint32_t a2 = *(const uint32_t*)(ap + 8);
            uint32_t a3 = *(const uint32_t*)(ap + 8 * 72 + 8);
            #pragma unroll
            for (int cf = 0; cf < 8; cf++) {
                int n = cf * 8 + qrow;
                int xorv = cf * 8;
                uint32_t b0 = *(const uint32_t*)&Bs[n * 72 + ((k0 + qk2) ^ xorv)];
                uint32_t b1 = *(const uint32_t*)&Bs[n * 72 + ((k0 + qk2 + 8) ^ xorv)];
                asm volatile(
                    "mma.sync.aligned.m16n8k16.row.col.f32.f16.f16.f32 "
                    "{%0,%1,%2,%3}, {%4,%5,%6,%7}, {%8,%9}, {%0,%1,%2,%3};"
                    : "+f"(acc[cf][0]), "+f"(acc[cf][1]), "+f"(acc[cf][2]), "+f"(acc[cf][3])
                    : "r"(a0), "r"(a1), "r"(a2), "r"(a3), "r"(b0), "r"(b1));
            }
        }
        // write khid back into As (bias + relu); warp-private rows, after all reads
        int row0 = wr + qrow;
        #pragma unroll
        for (int cf = 0; cf < 8; cf++) {
            int col = cf * 8 + q4 * 2;
            float bb0 = sb2[col], bb1 = sb2[col + 1];
            __half2 p0 = __floats2half2_rn(fmaxf(acc[cf][0] + bb0, 0.f),
                                           fmaxf(acc[cf][1] + bb1, 0.f));
            __half2 p1 = __floats2half2_rn(fmaxf(acc[cf][2] + bb0, 0.f),
                                           fmaxf(acc[cf][3] + bb1, 0.f));
            *(__half2*)&As[row0 * 72 + col]       = p0;
            *(__half2*)&As[(row0 + 8) * 72 + col] = p1;
        }
    }

    // ---- phase 2: 8 column blocks of W ----
    int wr2 = (w & 1) * 64;
    int wc2 = (w >> 1) * 32;
    uint32_t a_smem = (uint32_t)__cvta_generic_to_shared(As);
    uint32_t b_smem = (uint32_t)__cvta_generic_to_shared(Bs);
    int l15 = lane & 15;
    int i_base = wc2 >> 5;                    // 0 or... (wc2/32) in 0..3
    const __half* w3t = g_w3t[set];

    for (int cb = 0; cb < 8; cb++) {
        __syncthreads();                      // As writes + previous Bs reads done
        if (t < 128) sbias[t] = b3[cb * 128 + t];
        const __half* Bg = w3t + (size_t)cb * 128 * KW;
        #pragma unroll
        for (int i = 0; i < 4; i++) {
            int idx = t + 256 * i;             // 0..1023
            int n = idx >> 3, c8 = idx & 7;
            uint4 v = *(const uint4*)&Bg[n * KW + c8 * 8];
            int ksw = (c8 * 8) ^ (((n >> 3) & 7) * 8);
            *(uint4*)&Bs[n * 72 + ksw] = v;
        }
        __syncthreads();

        float acc[4][4][4];
        #pragma unroll
        for (int rf = 0; rf < 4; rf++)
            #pragma unroll
            for (int cf = 0; cf < 4; cf++)
                #pragma unroll
                for (int v = 0; v < 4; v++) acc[rf][cf][v] = 0.f;

        #pragma unroll
        for (int ks = 0; ks < 4; ks++) {
            int k0 = ks * 16;
            uint32_t a[4][4], b[4][2];
            #pragma unroll
            for (int rf = 0; rf < 4; rf++) {
                int row = wr2 + rf * 16 + l15;
                int col = k0 + (lane >> 4) * 8;
                uint32_t addr = a_smem + (uint32_t)(row * 72 + col) * 2;
                asm volatile(
                    "ldmatrix.sync.aligned.m8n8.x4.shared.b16 {%0,%1,%2,%3}, [%4];"
                    : "=r"(a[rf][0]), "=r"(a[rf][1]), "=r"(a[rf][2]), "=r"(a[rf][3])
                    : "r"(addr));
            }
            #pragma unroll
            for (int cf = 0; cf < 4; cf++) {
                int n = wc2 + cf * 8 + (l15 & 7);
                int kk = k0 + (l15 >> 3) * 8;
                int xorv = ((n >> 3) & 7) * 8;
                uint32_t addr = b_smem + (uint32_t)(n * 72 + (kk ^ xorv)) * 2;
                asm volatile(
                    "ldmatrix.sync.aligned.m8n8.x2.shared.b16 {%0,%1}, [%2];"
                    : "=r"(b[cf][0]), "=r"(b[cf][1])
                    : "r"(addr));
            }
            #pragma unroll
            for (int rf = 0; rf < 4; rf++)
                #pragma unroll
                for (int cf = 0; cf < 4; cf++)
                    asm volatile(
                        "mma.sync.aligned.m16n8k16.row.col.f32.f16.f16.f32 "
                        "{%0,%1,%2,%3}, {%4,%5,%6,%7}, {%8,%9}, {%0,%1,%2,%3};"
                        : "+f"(acc[rf][cf][0]), "+f"(acc[rf][cf][1]),
                          "+f"(acc[rf][cf][2]), "+f"(acc[rf][cf][3])
                        : "r"(a[rf][0]), "r"(a[rf][1]), "r"(a[rf][2]), "r"(a[rf][3]),
                          "r"(b[cf][0]), "r"(b[cf][1]));
        }

        int i_idx = cb * 4 + i_base;
        size_t colbase = (size_t)i_idx * 32 + q4 * 8;
        #pragma unroll
        for (int rf = 0; rf < 4; rf++) {
            int row = wr2 + rf * 16 + qrow;
            uint4 lo, hi;
            uint32_t* lop = (uint32_t*)&lo;
            uint32_t* hip = (uint32_t*)&hi;
            #pragma unroll
            for (int cf = 0; cf < 4; cf++) {
                int n32 = wc2 + cf * 8 + q4 * 2;
                float bb0 = sbias[n32], bb1 = sbias[n32 + 1];
                __half2 pl = __floats2half2_rn(acc[rf][cf][0] + bb0, acc[rf][cf][1] + bb1);
                __half2 ph = __floats2half2_rn(acc[rf][cf][2] + bb0, acc[rf][cf][3] + bb1);
                lop[cf] = *(uint32_t*)&pl;
                hip[cf] = *(uint32_t*)&ph;
            }
            *(uint4*)&g_Wh[((size_t)r0 + row) * 1024 + colbase]     = lo;
            *(uint4*)&g_Wh[((size_t)r0 + row + 8) * 1024 + colbase] = hi;
        }
    }
}

// ---------------- per-edge message (unscaled; scaling in node_update) ---------
__global__ void __launch_bounds__(256) edge_msg_kernel(const int* __restrict__ ei,
                                                       const int* __restrict__ eib)
{
    int e = (blockIdx.x * blockDim.x + threadIdx.x) >> 5;
    int lane = threadIdx.x & 31;
    if (e >= E_TOT) return;

    int src, dst; size_t wrow; float* aggp;
    if (e < E_MAIN) {
        src = ei[e]; dst = ei[E_MAIN + e];
        wrow = (size_t)e;
        aggp = g_agg1;
    } else {
        int eb = e - E_MAIN;
        src = eib[eb]; dst = eib[E_BND + eb];
        wrow = (size_t)E_PAD + eb;
        aggp = g_agg2;
    }

    float hv = g_h[src * WIDTH + lane];
    const __half* __restrict__ Wp = g_Wh + wrow * 1024;
    int q4 = lane & 3, m = lane >> 2;

    float acc[8];
    #pragma unroll
    for (int k = 0; k < 8; k++) acc[k] = 0.f;

    #pragma unroll
    for (int s = 0; s < 4; s++) {
        int i = m + 8 * s;
        uint4 v = *(const uint4*)(Wp + (size_t)i * 32 + q4 * 8);
        float hi = __shfl_sync(0xffffffffu, hv, i);
        float2 f0 = __half22float2(*reinterpret_cast<const __half2*>(&v.x));
        float2 f1 = __half22float2(*reinterpret_cast<const __half2*>(&v.y));
        float2 f2 = __half22float2(*reinterpret_cast<const __half2*>(&v.z));
        float2 f3 = __half22float2(*reinterpret_cast<const __half2*>(&v.w));
        acc[0] = fmaf(f0.x, hi, acc[0]); acc[1] = fmaf(f0.y, hi, acc[1]);
        acc[2] = fmaf(f1.x, hi, acc[2]); acc[3] = fmaf(f1.y, hi, acc[3]);
        acc[4] = fmaf(f2.x, hi, acc[4]); acc[5] = fmaf(f2.y, hi, acc[5]);
        acc[6] = fmaf(f3.x, hi, acc[6]); acc[7] = fmaf(f3.y, hi, acc[7]);
    }
    #pragma unroll
    for (int k = 0; k < 8; k++) {
        acc[k] += __shfl_xor_sync(0xffffffffu, acc[k], 4);
        acc[k] += __shfl_xor_sync(0xffffffffu, acc[k], 8);
        acc[k] += __shfl_xor_sync(0xffffffffu, acc[k], 16);
    }
    float out = acc[0];
    if (m == 1) out = acc[1];
    else if (m == 2) out = acc[2];
    else if (m == 3) out = acc[3];
    else if (m == 4) out = acc[4];
    else if (m == 5) out = acc[5];
    else if (m == 6) out = acc[6];
    else if (m == 7) out = acc[7];
    int o = (m >> 1) * 8 + q4 * 2 + (m & 1);
    atomicAdd(&aggp[dst * WIDTH + o], out);
}

// ---------------- node update: scale both agg sets, root, relu, +h0 -----------
__global__ void __launch_bounds__(256) node_update_kernel(int last,
                                                          const float* __restrict__ fc2w,
                                                          const float* __restrict__ fc2b,
                                                          float* __restrict__ out) {
    int n = (blockIdx.x * blockDim.x + threadIdx.x) >> 5;
    int lane = threadIdx.x & 31;
    if (n >= N_NODES) return;

    float s1 = 1.0f / fmaxf(g_cnt1[n], 1.0f);
    float s2 = 1.0f / fmaxf(g_cnt2[n], 1.0f);
    int idx = n * WIDTH + lane;
    float hv  = g_h[idx];
    float acc = g_agg1[idx] * s1 + g_agg2[idx] * s2 + g_biassum[lane];
    g_agg1[idx] = 0.f;
    g_agg2[idx] = 0.f;
    #pragma unroll
    for (int i = 0; i < 32; i++) {
        float hi = __shfl_sync(0xffffffffu, hv, i);
        acc = fmaf(hi, g_rootsum[i * 32 + lane], acc);
    }
    float hnew = fmaxf(acc, 0.f) + g_h0[idx];
    g_h[idx] = hnew;

    if (last) {
        float v = hnew * fc2w[lane];
        #pragma unroll
        for (int off = 16; off > 0; off >>= 1)
            v += __shfl_xor_sync(0xffffffffu, v, off);
        if (lane == 0) out[n] = v + fc2b[0];
    }
}

// ---------------- host orchestration ----------------
extern "C" void kernel_launch(void* const* d_in, const int* in_sizes, int n_in,
                              void* d_out, int out_size) {
    const float* x    = (const float*)d_in[0];
    const int*   ei   = (const int*)  d_in[1];
    const float* ea   = (const float*)d_in[2];
    const int*   eib  = (const int*)  d_in[3];
    const float* eab  = (const float*)d_in[4];
    const float* fc1w = (const float*)d_in[5];
    const float* fc1b = (const float*)d_in[6];
    const float* fc2w = (const float*)d_in[7];
    const float* fc2b = (const float*)d_in[8];
    const float* k1w1 = (const float*)d_in[9];
    const float* k1b1 = (const float*)d_in[10];
    const float* k1w2 = (const float*)d_in[11];
    const float* k1b2 = (const float*)d_in[12];
    const float* k1w3 = (const float*)d_in[13];
    const float* k1b3 = (const float*)d_in[14];
    const float* root1= (const float*)d_in[15];
    const float* bias1= (const float*)d_in[16];
    const float* k2w1 = (const float*)d_in[17];
    const float* k2b1 = (const float*)d_in[18];
    const float* k2w2 = (const float*)d_in[19];
    const float* k2b2 = (const float*)d_in[20];
    const float* k2w3 = (const float*)d_in[21];
    const float* k2b3 = (const float*)d_in[22];
    const float* root2= (const float*)d_in[23];
    const float* bias2= (const float*)d_in[24];
    float* out = (float*)d_out;

    // ncu profiles launch #4 -> fused_kernel
    setupA_kernel<<<(N_NODES * WIDTH + 255) / 256, 256>>>(x, fc1w, fc1b);      // 1
    setupB_kernel<<<(KW * 1024 + 255) / 256, 256>>>(root1, bias1, root2, bias2,
                                                    k1w2, k2w2, k1w3, k2w3);   // 2
    count_kernel<<<(E_TOT + 255) / 256, 256>>>(ei, eib);                       // 3
    fused_kernel<<<ROWS_TOT / 128, 256>>>(ea, eab,
                                          k1w1, k1b1, k1b2,
                                          k2w1, k2b1, k2b2,
                                          k1b3, k2b3);                         // 4

    for (int d = 0; d < DEPTH; d++) {
        edge_msg_kernel<<<(E_TOT * 32 + 255) / 256, 256>>>(ei, eib);
        node_update_kernel<<<(N_NODES * 32 + 255) / 256, 256>>>(
            d == DEPTH - 1 ? 1 : 0, fc2w, fc2b, out);
    }
}